// round 16
// baseline (speedup 1.0000x reference)
#include <cuda_runtime.h>

// ---------------------------------------------------------------------------
// MSGMS loss, 4-scale pyramid.
//  Kernel 1 (graypyr_k): fused grayscale + avg-pool pyramid (~68% DRAM, floor).
//  Kernel 2 (gms_all_k): 64x64 tiles, 128 threads. Stage A stages the gray
//     tile in smem (coalesced, guarded per-quad). Then each thread walks a
//     4-col x 8-row strip, keeping 3 gray rows (8 cols) + 3 median rows
//     (6 cols) in REGISTERS: median/Prewitt/GMS never touch smem.
//     One barrier per tile. Per-block partial -> g_partial[bid].
//  Kernel 3 (finalize_k): fixed-order deterministic sum.
// ---------------------------------------------------------------------------

#define C_GMS 0.0026f

static constexpr int NB   = 16;
static constexpr int HW0  = 512 * 512;
static constexpr int OFF0 = 0;
static constexpr int OFF1 = OFF0 + 16 * 512 * 512;
static constexpr int OFF2 = OFF1 + 16 * 256 * 256;
static constexpr int OFF3 = OFF2 + 16 * 128 * 128;
static constexpr int GTOT = OFF3 + 16 * 64 * 64;

// 64x64 tiles
static constexpr int N0 = 8 * 8 * NB;     // 1024 @512
static constexpr int N1 = 4 * 4 * NB;     // 256  @256
static constexpr int N2 = 2 * 2 * NB;     // 64   @128
static constexpr int N3 = 1 * 1 * NB;     // 16   @64
static constexpr int NBLK = N0 + N1 + N2 + N3;  // 1360

__device__ float  g_gray[2][GTOT];
__device__ double g_partial[NBLK];

// ---------------------------------------------------------------------------
// Kernel 1: grayscale + pooled pyramid (register-fused gray->L1, 10KB smem).
// ---------------------------------------------------------------------------
__global__ __launch_bounds__(256) void graypyr_k(const float* __restrict__ Ii,
                                                 const float* __restrict__ Ir) {
    const int s = blockIdx.x;   // stripe 0..63 (L0 rows 8s..8s+7)
    const int b = blockIdx.y;   // batch
    const int tid = threadIdx.x;
    __shared__ float s1[2][4][256];
    __shared__ float s2[2][2][128];
    const float inv3 = 1.0f / 3.0f;

    for (int i = tid; i < 1024; i += 256) {
        int img = i >> 9;
        int rem = i & 511;
        int r1  = rem >> 7;
        int k   = rem & 127;
        const float* base = (img ? Ir : Ii) + (size_t)b * 3 * HW0
                            + (size_t)(s * 8 + 2 * r1) * 512 + 4 * k;
        float4 a0 = *(const float4*)base;
        float4 a1 = *(const float4*)(base + HW0);
        float4 a2 = *(const float4*)(base + 2 * HW0);
        float4 g0 = { (a0.x + a1.x + a2.x) * inv3, (a0.y + a1.y + a2.y) * inv3,
                      (a0.z + a1.z + a2.z) * inv3, (a0.w + a1.w + a2.w) * inv3 };
        const float* baseb = base + 512;
        float4 c0 = *(const float4*)baseb;
        float4 c1 = *(const float4*)(baseb + HW0);
        float4 c2 = *(const float4*)(baseb + 2 * HW0);
        float4 g1 = { (c0.x + c1.x + c2.x) * inv3, (c0.y + c1.y + c2.y) * inv3,
                      (c0.z + c1.z + c2.z) * inv3, (c0.w + c1.w + c2.w) * inv3 };
        float* L0 = &g_gray[img][(size_t)b * HW0 + (size_t)(s * 8 + 2 * r1) * 512 + 4 * k];
        *(float4*)L0         = g0;
        *(float4*)(L0 + 512) = g1;
        float2 l1 = { (g0.x + g0.y + g1.x + g1.y) * 0.25f,
                      (g0.z + g0.w + g1.z + g1.w) * 0.25f };
        *(float2*)&s1[img][r1][2 * k] = l1;
        *(float2*)&g_gray[img][OFF1 + (size_t)b * 256 * 256 + (size_t)(s * 4 + r1) * 256 + 2 * k] = l1;
    }
    __syncthreads();

    for (int i = tid; i < 512; i += 256) {
        int img = i >> 8;
        int rem = i & 255;
        int r   = rem >> 7;
        int c   = rem & 127;
        float2 t0 = *(const float2*)&s1[img][2 * r][2 * c];
        float2 t1 = *(const float2*)&s1[img][2 * r + 1][2 * c];
        float v = (t0.x + t0.y + t1.x + t1.y) * 0.25f;
        s2[img][r][c] = v;
        g_gray[img][OFF2 + (size_t)b * 128 * 128 + (size_t)(s * 2 + r) * 128 + c] = v;
    }
    __syncthreads();

    if (tid < 128) {
        int img = tid >> 6;
        int c   = tid & 63;
        float2 t0 = *(const float2*)&s2[img][0][2 * c];
        float2 t1 = *(const float2*)&s2[img][1][2 * c];
        float v = (t0.x + t0.y + t1.x + t1.y) * 0.25f;
        g_gray[img][OFF3 + (size_t)b * 64 * 64 + (size_t)s * 64 + c] = v;
    }
}

// ---------------------------------------------------------------------------
// GMS: 64x64 tile staged in smem; register-rolling strips for BC+D.
// ---------------------------------------------------------------------------
struct Smem {
    float g[2][68][72];   // gray: row lr = gray row OY-1+lr, col lc = OX-4+lc
    float wsum[4];
};

__device__ __forceinline__ float med3f(float a, float b, float c) {
    return fmaxf(fminf(a, b), fminf(fmaxf(a, b), c));
}
__device__ __forceinline__ void sort3f(float& a, float& b, float& c) {
    float t;
    t = fminf(a, b); b = fmaxf(a, b); a = t;
    t = fminf(b, c); c = fmaxf(b, c); b = t;
    t = fminf(a, b); b = fmaxf(a, b); a = t;
}

// read 8 gray cols (c0-1 .. c0+6) of smem row lr into o[8]
__device__ __forceinline__ void ld8(const float (&gr)[68][72], int lr, int lc0,
                                    float* o) {
    o[0] = gr[lr][lc0 - 1];
    float4 q0 = *(const float4*)&gr[lr][lc0];
    float4 q1 = *(const float4*)&gr[lr][lc0 + 4];
    o[1] = q0.x; o[2] = q0.y; o[3] = q0.z; o[4] = q0.w;
    o[5] = q1.x; o[6] = q1.y; o[7] = q1.z;
}

// med row: 3 gray rows (8 cols) -> 6 medians (med cols c0..c0+5)
__device__ __forceinline__ void med_row6(const float* a, const float* b,
                                         const float* c, float* m) {
    float lo[8], mi[8], hi[8];
#pragma unroll
    for (int j = 0; j < 8; j++) {
        float v0 = a[j], v1 = b[j], v2 = c[j];
        sort3f(v0, v1, v2);
        lo[j] = v0; mi[j] = v1; hi[j] = v2;
    }
#pragma unroll
    for (int t = 0; t < 6; t++) {
        float L  = fmaxf(fmaxf(lo[t], lo[t + 1]), lo[t + 2]);
        float M  = med3f(mi[t], mi[t + 1], mi[t + 2]);
        float Hh = fminf(fminf(hi[t], hi[t + 1]), hi[t + 2]);
        m[t] = med3f(L, M, Hh);
    }
}

template <int H, int W, int LOGT>
__device__ __forceinline__ void gms_tile(Smem& sm, int local, int off, int gbid) {
    constexpr int T = 1 << LOGT;              // 64-px tiles per dim
    const int bx = local & (T - 1);
    const int by = (local >> LOGT) & (T - 1);
    const int b  = local >> (2 * LOGT);
    const int OX = bx * 64;
    const int OY = by * 64;
    const int tid = threadIdx.x;

    const float* __restrict__ g0 = &g_gray[0][off + (size_t)b * H * W];
    const float* __restrict__ g1 = &g_gray[1][off + (size_t)b * H * W];

    // ---- Stage A: gray tile rows OY-1..OY+66, cols OX-4..OX+67 (guarded) ----
    for (int i = tid; i < 2448; i += 128) {     // 2 img x 68 rows x 18 quads
        int img = (i >= 1224);
        int rem = i - img * 1224;
        int r   = rem / 18;
        int k   = rem - 18 * r;
        int gy  = OY - 1 + r;
        int gc  = OX - 4 + 4 * k;
        const float* g = img ? g1 : g0;
        float vv[4] = {0.f, 0.f, 0.f, 0.f};
        if ((unsigned)gy < (unsigned)H) {
            if (gc >= 0 && gc + 4 <= W) {
                *(float4*)vv = *(const float4*)(g + (size_t)gy * W + gc);
            } else {
#pragma unroll
                for (int j = 0; j < 4; j++) {
                    int x = gc + j;
                    if ((unsigned)x < (unsigned)W)
                        vv[j] = __ldg(g + (size_t)gy * W + x);
                }
            }
        }
        *(float4*)&sm.g[img][r][4 * k] = *(float4*)vv;
    }
    __syncthreads();

    // ---- Register-rolling strip: 4 cols x 8 rows per thread ----
    const int ks   = tid & 15;      // col strip 0..15
    const int band = tid >> 4;      // row band 0..7
    const int lc0  = 4 * ks + 4;    // local col of strip col 0
    const int c0   = OX + 4 * ks;   // global
    const int j0   = 8 * band;      // local output row base

    float gB[2][8], gC[2][8], gD[2][8];
    float m0[2][6], m1[2][6], m2[2][6];

    // prologue: med rows j0, j0+1 (smem rows j0..j0+3 = gray rows j0-1..j0+2)
#pragma unroll
    for (int im = 0; im < 2; im++) {
        float t0[8], t1[8];
        ld8(sm.g[im], j0 + 0, lc0, t0);
        ld8(sm.g[im], j0 + 1, lc0, t1);
        ld8(sm.g[im], j0 + 2, lc0, gB[im]);
        ld8(sm.g[im], j0 + 3, lc0, gC[im]);
        med_row6(t0, t1, gB[im], m0[im]);
        med_row6(t1, gB[im], gC[im], m1[im]);
    }

    const float C9 = 9.0f * C_GMS;
    float acc = 0.0f;
#pragma unroll
    for (int jj = 0; jj < 8; jj++) {
        const int j = j0 + jj;                  // local output row
#pragma unroll
        for (int im = 0; im < 2; im++) {
            ld8(sm.g[im], j + 4, lc0, gD[im]);  // gray row j+3
            med_row6(gB[im], gC[im], gD[im], m2[im]);
        }
        float t[2][4];
#pragma unroll
        for (int im = 0; im < 2; im++) {
            float cs[6];
#pragma unroll
            for (int c = 0; c < 6; c++) cs[c] = m0[im][c] + m1[im][c] + m2[im][c];
#pragma unroll
            for (int x = 0; x < 4; x++) {
                float gx = cs[x + 2] - cs[x];
                float gy = (m0[im][x] + m0[im][x + 1] + m0[im][x + 2])
                         - (m2[im][x] + m2[im][x + 1] + m2[im][x + 2]);
                t[im][x] = gx * gx + gy * gy;
            }
        }
        if (OY + j <= H - 3) {
#pragma unroll
            for (int x = 0; x < 4; x++) {
                if (c0 + x <= W - 3) {
                    float p = t[0][x] * t[1][x];
                    float s = p * rsqrtf(p + 1e-30f);   // sqrt(p), 0-safe
                    acc += 1.0f - __fdividef(2.0f * s + C9, t[0][x] + t[1][x] + C9);
                }
            }
        }
        // shift (register renaming under full unroll)
#pragma unroll
        for (int c = 0; c < 6; c++) {
            m0[0][c] = m1[0][c]; m0[1][c] = m1[1][c];
            m1[0][c] = m2[0][c]; m1[1][c] = m2[1][c];
        }
#pragma unroll
        for (int x = 0; x < 8; x++) {
            gB[0][x] = gC[0][x]; gB[1][x] = gC[1][x];
            gC[0][x] = gD[0][x]; gC[1][x] = gD[1][x];
        }
    }

    // ---- block reduction (4 warps) ----
#pragma unroll
    for (int o = 16; o > 0; o >>= 1) acc += __shfl_down_sync(0xffffffffu, acc, o);
    if ((tid & 31) == 0) sm.wsum[tid >> 5] = acc;
    __syncthreads();
    if (tid < 4) {
        float s = sm.wsum[tid];
        s += __shfl_down_sync(0xfu, s, 2);
        s += __shfl_down_sync(0xfu, s, 1);
        if (tid == 0) {
            constexpr float wgt = 1.0f / (4.0f * (float)NB * (float)(H - 2) * (float)(W - 2));
            g_partial[gbid] = (double)(s * wgt);
        }
    }
}

__global__ __launch_bounds__(128) void gms_all_k() {
    __shared__ Smem sm;
    const int bid = blockIdx.x;
    if (bid < N0) {
        gms_tile<512, 512, 3>(sm, bid, OFF0, bid);
    } else if (bid < N0 + N1) {
        gms_tile<256, 256, 2>(sm, bid - N0, OFF1, bid);
    } else if (bid < N0 + N1 + N2) {
        gms_tile<128, 128, 1>(sm, bid - N0 - N1, OFF2, bid);
    } else {
        gms_tile<64, 64, 0>(sm, bid - N0 - N1 - N2, OFF3, bid);
    }
}

// ---------------------------------------------------------------------------
// Kernel 3: deterministic fixed-order reduction of per-block partials.
// ---------------------------------------------------------------------------
__global__ __launch_bounds__(256) void finalize_k(float* __restrict__ out) {
    __shared__ double ws[8];
    double s = 0.0;
    for (int i = threadIdx.x; i < NBLK; i += 256) s += g_partial[i];
#pragma unroll
    for (int o = 16; o > 0; o >>= 1) s += __shfl_down_sync(0xffffffffu, s, o);
    if ((threadIdx.x & 31) == 0) ws[threadIdx.x >> 5] = s;
    __syncthreads();
    if (threadIdx.x < 8) {
        double t = ws[threadIdx.x];
#pragma unroll
        for (int o = 4; o > 0; o >>= 1) t += __shfl_down_sync(0xffu, t, o);
        if (threadIdx.x == 0) out[0] = (float)t;
    }
}

// ---------------------------------------------------------------------------
extern "C" void kernel_launch(void* const* d_in, const int* in_sizes, int n_in,
                              void* d_out, int out_size) {
    const float* Ii = (const float*)d_in[0];
    const float* Ir = (const float*)d_in[1];
    float* out = (float*)d_out;

    graypyr_k<<<dim3(64, NB), 256>>>(Ii, Ir);
    gms_all_k<<<NBLK, 128>>>();
    finalize_k<<<1, 256>>>(out);
}

// round 17
// speedup vs baseline: 1.1678x; 1.1678x over previous
#include <cuda_runtime.h>

// ---------------------------------------------------------------------------
// MSGMS loss, 4-scale pyramid.  (R12 structure + widened BC tasks)
//  Kernel 1 (graypyr_k): fused grayscale + avg-pool pyramid (~68% DRAM, floor).
//  Kernel 2 (gms_all_k): ALL 4 scales, one launch, 64x32 tiles, 512 threads.
//     stage A : gray tile (68x48) via unified per-quad loads
//     stage BC: fused vertical sort3 + horizontal median-of-9, 8 medians/task
//               (12 LDS-issues + 10 sort3 per 8 medians)
//     stage D : Prewitt + gmap via MUFU intrinsics; 4 px/thread
//     -> per-block partial in g_partial[bid]
//  Kernel 3 (finalize_k): fixed-order deterministic sum.
// ---------------------------------------------------------------------------

#define C_GMS 0.0026f

static constexpr int NB   = 16;
static constexpr int HW0  = 512 * 512;
static constexpr int OFF0 = 0;
static constexpr int OFF1 = OFF0 + 16 * 512 * 512;
static constexpr int OFF2 = OFF1 + 16 * 256 * 256;
static constexpr int OFF3 = OFF2 + 16 * 128 * 128;
static constexpr int GTOT = OFF3 + 16 * 64 * 64;

// 64-row x 32-col tiles
static constexpr int N0 = 16 * 8 * NB;    // 2048 tiles @512
static constexpr int N1 = 8 * 4 * NB;     // 512  @256
static constexpr int N2 = 4 * 2 * NB;     // 128  @128
static constexpr int N3 = 2 * 1 * NB;     // 32   @64
static constexpr int NBLK = N0 + N1 + N2 + N3;  // 2720

__device__ float  g_gray[2][GTOT];
__device__ double g_partial[NBLK];

// ---------------------------------------------------------------------------
// Kernel 1: grayscale + pooled pyramid (register-fused gray->L1, 10KB smem).
// ---------------------------------------------------------------------------
__global__ __launch_bounds__(256) void graypyr_k(const float* __restrict__ Ii,
                                                 const float* __restrict__ Ir) {
    const int s = blockIdx.x;   // stripe 0..63 (L0 rows 8s..8s+7)
    const int b = blockIdx.y;   // batch
    const int tid = threadIdx.x;
    __shared__ float s1[2][4][256];
    __shared__ float s2[2][2][128];
    const float inv3 = 1.0f / 3.0f;

    for (int i = tid; i < 1024; i += 256) {
        int img = i >> 9;
        int rem = i & 511;
        int r1  = rem >> 7;      // L1 row 0..3
        int k   = rem & 127;     // col-pair (L0 cols 4k..4k+3)
        const float* base = (img ? Ir : Ii) + (size_t)b * 3 * HW0
                            + (size_t)(s * 8 + 2 * r1) * 512 + 4 * k;
        float4 a0 = *(const float4*)base;
        float4 a1 = *(const float4*)(base + HW0);
        float4 a2 = *(const float4*)(base + 2 * HW0);
        float4 g0 = { (a0.x + a1.x + a2.x) * inv3, (a0.y + a1.y + a2.y) * inv3,
                      (a0.z + a1.z + a2.z) * inv3, (a0.w + a1.w + a2.w) * inv3 };
        const float* baseb = base + 512;
        float4 c0 = *(const float4*)baseb;
        float4 c1 = *(const float4*)(baseb + HW0);
        float4 c2 = *(const float4*)(baseb + 2 * HW0);
        float4 g1 = { (c0.x + c1.x + c2.x) * inv3, (c0.y + c1.y + c2.y) * inv3,
                      (c0.z + c1.z + c2.z) * inv3, (c0.w + c1.w + c2.w) * inv3 };
        float* L0 = &g_gray[img][(size_t)b * HW0 + (size_t)(s * 8 + 2 * r1) * 512 + 4 * k];
        *(float4*)L0         = g0;
        *(float4*)(L0 + 512) = g1;
        float2 l1 = { (g0.x + g0.y + g1.x + g1.y) * 0.25f,
                      (g0.z + g0.w + g1.z + g1.w) * 0.25f };
        *(float2*)&s1[img][r1][2 * k] = l1;
        *(float2*)&g_gray[img][OFF1 + (size_t)b * 256 * 256 + (size_t)(s * 4 + r1) * 256 + 2 * k] = l1;
    }
    __syncthreads();

    for (int i = tid; i < 512; i += 256) {
        int img = i >> 8;
        int rem = i & 255;
        int r   = rem >> 7;
        int c   = rem & 127;
        float2 t0 = *(const float2*)&s1[img][2 * r][2 * c];
        float2 t1 = *(const float2*)&s1[img][2 * r + 1][2 * c];
        float v = (t0.x + t0.y + t1.x + t1.y) * 0.25f;
        s2[img][r][c] = v;
        g_gray[img][OFF2 + (size_t)b * 128 * 128 + (size_t)(s * 2 + r) * 128 + c] = v;
    }
    __syncthreads();

    if (tid < 128) {
        int img = tid >> 6;
        int c   = tid & 63;
        float2 t0 = *(const float2*)&s2[img][0][2 * c];
        float2 t1 = *(const float2*)&s2[img][1][2 * c];
        float v = (t0.x + t0.y + t1.x + t1.y) * 0.25f;
        g_gray[img][OFF3 + (size_t)b * 64 * 64 + (size_t)s * 64 + c] = v;
    }
}

// ---------------------------------------------------------------------------
// Fused GMS tile: 64 rows x 32 cols output, 512 threads.
// gray stride 48 (col cc = OX-4+cc), med stride 40; quads 16B-aligned.
// ---------------------------------------------------------------------------
struct Smem {
    float g[2][68][48];     // gray: row r = gray row OY-1+r
    float med[2][66][40];   // median-of-9 tile
    float wsum[16];
};

__device__ __forceinline__ float med3f(float a, float b, float c) {
    return fmaxf(fminf(a, b), fminf(fmaxf(a, b), c));
}
__device__ __forceinline__ void sort3f(float& a, float& b, float& c) {
    float t;
    t = fminf(a, b); b = fmaxf(a, b); a = t;
    t = fminf(b, c); c = fmaxf(b, c); b = t;
    t = fminf(a, b); b = fmaxf(a, b); a = t;
}

template <int H, int W, int LOGTX>
__device__ __forceinline__ void gms_tile(Smem& sm, int local, int off, int gbid) {
    constexpr int TX = 1 << LOGTX;            // col tiles (W/32)
    constexpr int LOGTY = (LOGTX > 0) ? (LOGTX - 1) : 0;
    constexpr int TY = 1 << LOGTY;            // row tiles (H/64)
    const int bx = local & (TX - 1);
    const int by = (local >> LOGTX) & (TY - 1);
    const int b  = local >> (LOGTX + LOGTY);
    const int OX = bx * 32;
    const int OY = by * 64;
    const int tid = threadIdx.x;

    const float* __restrict__ g0 = &g_gray[0][off + (size_t)b * H * W];
    const float* __restrict__ g1 = &g_gray[1][off + (size_t)b * H * W];

    const bool interior = (OX >= 4) && (OX + 36 <= W) && (OY >= 1) && (OY + 67 <= H);

    // ---- Stage A: gray tile (2 img x 68 rows x 12 quads = 1632 tasks) ----
    for (int i = tid; i < 1632; i += 512) {
        int img = (i >= 816);
        int rem = i - img * 816;
        int r   = rem / 12;
        int k   = rem - 12 * r;
        int gy  = OY - 1 + r;
        int gc  = OX - 4 + 4 * k;
        const float* g = img ? g1 : g0;
        float vv[4] = {0.f, 0.f, 0.f, 0.f};
        if ((unsigned)gy < (unsigned)H) {
            if (gc >= 0 && gc + 4 <= W) {
                *(float4*)vv = *(const float4*)(g + (size_t)gy * W + gc);
            } else {
#pragma unroll
                for (int j = 0; j < 4; j++) {
                    int x = gc + j;
                    if ((unsigned)x < (unsigned)W)
                        vv[j] = __ldg(g + (size_t)gy * W + x);
                }
            }
        }
        *(float4*)&sm.g[img][r][4 * k] = *(float4*)vv;
    }
    __syncthreads();

    // ---- Stage BC (fused): 8 medians/task (2 img x 66 rows x 5 groups = 660) ----
    // Med col j uses gray cols j+3..j+5. Group covers med cols c0..c0+7
    // -> gray cols c0+3..c0+12: 2 scalars + 2 aligned quads per row.
    for (int i = tid; i < 660; i += 512) {
        int img = (i >= 330);
        int rem = i - img * 330;
        int r   = rem / 5;
        int grp = rem - 5 * r;
        int c0  = 8 * grp;
        float a[3][10];
#pragma unroll
        for (int rr = 0; rr < 3; rr++) {
            a[rr][0] = sm.g[img][r + rr][c0 + 3];
            *(float4*)&a[rr][1] = *(const float4*)&sm.g[img][r + rr][c0 + 4];
            *(float4*)&a[rr][5] = *(const float4*)&sm.g[img][r + rr][c0 + 8];
            a[rr][9] = sm.g[img][r + rr][c0 + 12];
        }
        float lo[10], mi[10], hi[10];
#pragma unroll
        for (int j = 0; j < 10; j++) {
            float v0 = a[0][j], v1 = a[1][j], v2 = a[2][j];
            sort3f(v0, v1, v2);
            lo[j] = v0; mi[j] = v1; hi[j] = v2;
        }
        float out[8];
#pragma unroll
        for (int m = 0; m < 8; m++) {
            float L  = fmaxf(fmaxf(lo[m], lo[m + 1]), lo[m + 2]);
            float M  = med3f(mi[m], mi[m + 1], mi[m + 2]);
            float Hh = fminf(fminf(hi[m], hi[m + 1]), hi[m + 2]);
            out[m] = med3f(L, M, Hh);
        }
        *(float4*)&sm.med[img][r][c0]     = *(float4*)&out[0];
        *(float4*)&sm.med[img][r][c0 + 4] = *(float4*)&out[4];
    }
    __syncthreads();

    // ---- Stage D: Prewitt + GMS, 4 px/thread via 12 LDS.128 ----
    const float C9 = 9.0f * C_GMS;
    const int q   = tid & 7;          // col quad: output cols OX+4q..OX+4q+3
    const int row = tid >> 3;         // output row OY+row, 0..63
    float t[2][4];
#pragma unroll
    for (int img = 0; img < 2; img++) {
        float r0[8], r1[8], r2[8];
        *(float4*)&r0[0] = *(const float4*)&sm.med[img][row][4 * q];
        *(float4*)&r0[4] = *(const float4*)&sm.med[img][row][4 * q + 4];
        *(float4*)&r1[0] = *(const float4*)&sm.med[img][row + 1][4 * q];
        *(float4*)&r1[4] = *(const float4*)&sm.med[img][row + 1][4 * q + 4];
        *(float4*)&r2[0] = *(const float4*)&sm.med[img][row + 2][4 * q];
        *(float4*)&r2[4] = *(const float4*)&sm.med[img][row + 2][4 * q + 4];
        float cs[6];
#pragma unroll
        for (int c = 0; c < 6; c++) cs[c] = r0[c] + r1[c] + r2[c];
#pragma unroll
        for (int j = 0; j < 4; j++) {
            float u = cs[j + 2] - cs[j];
            float v = (r0[j] + r0[j + 1] + r0[j + 2]) - (r2[j] + r2[j + 1] + r2[j + 2]);
            t[img][j] = u * u + v * v;
        }
    }
    float acc = 0.0f;
#pragma unroll
    for (int j = 0; j < 4; j++) {
        bool valid = interior || ((OY + row < H - 2) && (OX + 4 * q + j < W - 2));
        if (valid) {
            float p = t[0][j] * t[1][j];
            float s = p * rsqrtf(p + 1e-30f);      // sqrt(p), branchless, 0-safe
            float num = 2.0f * s + C9;
            float den = t[0][j] + t[1][j] + C9;
            acc += 1.0f - __fdividef(num, den);
        }
    }

    // ---- block reduction (16 warps) ----
#pragma unroll
    for (int o = 16; o > 0; o >>= 1) acc += __shfl_down_sync(0xffffffffu, acc, o);
    if ((tid & 31) == 0) sm.wsum[tid >> 5] = acc;
    __syncthreads();
    if (tid < 16) {
        float s = sm.wsum[tid];
#pragma unroll
        for (int o = 8; o > 0; o >>= 1) s += __shfl_down_sync(0xffffu, s, o);
        if (tid == 0) {
            constexpr float wgt = 1.0f / (4.0f * (float)NB * (float)(H - 2) * (float)(W - 2));
            g_partial[gbid] = (double)(s * wgt);
        }
    }
}

__global__ __launch_bounds__(512) void gms_all_k() {
    __shared__ Smem sm;
    const int bid = blockIdx.x;
    if (bid < N0) {
        gms_tile<512, 512, 4>(sm, bid, OFF0, bid);
    } else if (bid < N0 + N1) {
        gms_tile<256, 256, 3>(sm, bid - N0, OFF1, bid);
    } else if (bid < N0 + N1 + N2) {
        gms_tile<128, 128, 2>(sm, bid - N0 - N1, OFF2, bid);
    } else {
        gms_tile<64, 64, 1>(sm, bid - N0 - N1 - N2, OFF3, bid);
    }
}

// ---------------------------------------------------------------------------
// Kernel 3: deterministic fixed-order reduction of per-block partials.
// ---------------------------------------------------------------------------
__global__ __launch_bounds__(256) void finalize_k(float* __restrict__ out) {
    __shared__ double ws[8];
    double s = 0.0;
    for (int i = threadIdx.x; i < NBLK; i += 256) s += g_partial[i];
#pragma unroll
    for (int o = 16; o > 0; o >>= 1) s += __shfl_down_sync(0xffffffffu, s, o);
    if ((threadIdx.x & 31) == 0) ws[threadIdx.x >> 5] = s;
    __syncthreads();
    if (threadIdx.x < 8) {
        double t = ws[threadIdx.x];
#pragma unroll
        for (int o = 4; o > 0; o >>= 1) t += __shfl_down_sync(0xffu, t, o);
        if (threadIdx.x == 0) out[0] = (float)t;
    }
}

// ---------------------------------------------------------------------------
extern "C" void kernel_launch(void* const* d_in, const int* in_sizes, int n_in,
                              void* d_out, int out_size) {
    const float* Ii = (const float*)d_in[0];
    const float* Ir = (const float*)d_in[1];
    float* out = (float*)d_out;

    graypyr_k<<<dim3(64, NB), 256>>>(Ii, Ir);
    gms_all_k<<<NBLK, 512>>>();
    finalize_k<<<1, 256>>>(out);
}